// round 2
// baseline (speedup 1.0000x reference)
#include <cuda_runtime.h>
#include <cuda_bf16.h>
#include <cstdint>

#define M_TOTAL 8192
#define K_TOTAL 4608
#define N_TOTAL 4608
#define GSIZE   36

// -------- device scratch (static: no allocation in kernel_launch) --------
__device__ __nv_bfloat16 g_qx[(size_t)M_TOTAL * K_TOTAL];  // 75.5 MB
__device__ __nv_bfloat16 g_qw[(size_t)N_TOTAL * K_TOTAL];  // 42.5 MB

// ============================ helpers ============================
__device__ __forceinline__ uint32_t smem_u32(const void* p) {
    uint32_t a;
    asm("{ .reg .u64 t; cvta.to.shared.u64 t, %1; cvt.u32.u64 %0, t; }"
        : "=r"(a) : "l"(p));
    return a;
}

#define SW128(o) ((o) ^ (((o) >> 3) & 0x70))

__device__ __forceinline__ void cp16(uint32_t saddr, const void* g) {
    asm volatile("cp.async.cg.shared.global [%0], [%1], 16;"
                 :: "r"(saddr), "l"(g) : "memory");
}
#define CP_COMMIT() asm volatile("cp.async.commit_group;" ::: "memory")
#define CP_WAIT0()  asm volatile("cp.async.wait_group 0;" ::: "memory")

#define LDSM_X4(r, addr) \
    asm volatile("ldmatrix.sync.aligned.m8n8.x4.shared.b16 {%0,%1,%2,%3}, [%4];" \
        : "=r"((r)[0]), "=r"((r)[1]), "=r"((r)[2]), "=r"((r)[3]) : "r"(addr))

#define MMA16816(d, a, b0, b1) \
    asm volatile("mma.sync.aligned.m16n8k16.row.col.f32.bf16.bf16.f32 " \
        "{%0,%1,%2,%3}, {%4,%5,%6,%7}, {%8,%9}, {%0,%1,%2,%3};" \
        : "+f"((d)[0]), "+f"((d)[1]), "+f"((d)[2]), "+f"((d)[3]) \
        : "r"((a)[0]), "r"((a)[1]), "r"((a)[2]), "r"((a)[3]), "r"(b0), "r"(b1))

// ============================ Quantize ============================
// One warp per group of 36. Shared exponent from fp32 bits of absmax
// (floor(log2) == unbiased exponent for normals); trunc/scale are
// power-of-two multiplies -> exact; result has <=8 significand bits ->
// exact in bf16.
__global__ void __launch_bounds__(256) bfp_quant(const float* __restrict__ in,
                                                 __nv_bfloat16* __restrict__ out,
                                                 int ngroups) {
    int g    = (int)((blockIdx.x * 256u + threadIdx.x) >> 5);
    int lane = threadIdx.x & 31;
    if (g >= ngroups) return;
    size_t base = (size_t)g * GSIZE;

    float x0 = in[base + lane];
    float x1 = (lane < 4) ? in[base + 32 + lane] : 0.0f;

    float m = fmaxf(fabsf(x0), fabsf(x1));
    #pragma unroll
    for (int o = 16; o; o >>= 1)
        m = fmaxf(m, __shfl_xor_sync(0xFFFFFFFFu, m, o));

    if (m > 0.0f) {
        int e = (int)((__float_as_uint(m) >> 23) & 0xFF) - 127;
        float stp = __int_as_float((uint32_t)(e - 7 + 127) << 23);  // 2^(e-7)
        float inv = __int_as_float((uint32_t)(7 - e + 127) << 23);  // 2^(7-e)
        x0 = truncf(x0 * inv) * stp;
        x1 = truncf(x1 * inv) * stp;
    }
    out[base + lane] = __float2bfloat16(x0);
    if (lane < 4) out[base + 32 + lane] = __float2bfloat16(x1);
}

// ============================ GEMM ============================
// D[8192,4608] = qx @ qw^T + bias   (TN: both operands K-major)
// CTA: 128x128 tile, BK=64. 8 warps (2M x 4N), warp tile 64x32.
// mma.sync.m16n8k16 bf16 -> fp32 regs; ldmatrix from SW128 smem;
// cp.async double buffering.
#define BM 128
#define BN 128
#define BK 64
#define KITERS (K_TOTAL / BK)       // 72
#define BUF_BYTES 32768             // A tile 16KB + B tile 16KB
#define SMEM_BYTES (2 * BUF_BYTES)  // 64KB

__global__ void __launch_bounds__(256, 2)
bfp_gemm(const float* __restrict__ bias, float* __restrict__ out) {
    extern __shared__ char smem[];
    const uint32_t sb = smem_u32(smem);
    const int tid  = threadIdx.x;
    const int wid  = tid >> 5;
    const int lane = tid & 31;
    const int n0 = blockIdx.x * BN;
    const int m0 = blockIdx.y * BM;

    const int m_warp = (wid & 1) * 64;   // 2 warps along M
    const int n_warp = (wid >> 1) * 32;  // 4 warps along N

    const __nv_bfloat16* Ag = g_qx + (size_t)m0 * K_TOTAL;
    const __nv_bfloat16* Bg = g_qw + (size_t)n0 * K_TOTAL;

    // --- async tile loader: A[128 x 64] + B[128 x 64] bf16, SW128 rows of 128B
    const int ldr = tid >> 3;         // row 0..31 base (+32*j)
    const int ldc = tid & 7;          // 16B chunk 0..7
    auto load_tiles = [&](int it) {
        const __nv_bfloat16* Ak = Ag + it * BK;
        const __nv_bfloat16* Bk = Bg + it * BK;
        const uint32_t base = sb + (uint32_t)(it & 1) * BUF_BYTES;
        #pragma unroll
        for (int j = 0; j < 4; ++j) {
            int r = ldr + j * 32;
            uint32_t soff = SW128((uint32_t)(r * 128 + ldc * 16));
            cp16(base + soff,         Ak + (size_t)r * K_TOTAL + ldc * 8);
            cp16(base + 16384 + soff, Bk + (size_t)r * K_TOTAL + ldc * 8);
        }
        CP_COMMIT();
    };

    float acc[4][4][4];
    #pragma unroll
    for (int i = 0; i < 4; ++i)
        #pragma unroll
        for (int j = 0; j < 4; ++j)
            #pragma unroll
            for (int c = 0; c < 4; ++c) acc[i][j][c] = 0.0f;

    load_tiles(0);

    // ldmatrix lane addressing (x4): lanes 0-7 mat0, 8-15 mat1, 16-23 mat2, 24-31 mat3
    // mat0: rows 0-7 k-low, mat1: rows 8-15 k-low, mat2: rows 0-7 k-high, mat3: rows 8-15 k-high
    const int r_in  = (lane & 7) + ((lane >> 3) & 1) * 8;
    const int khalf = lane >> 4;

    for (int it = 0; it < KITERS; ++it) {
        CP_WAIT0();
        __syncthreads();
        if (it + 1 < KITERS) load_tiles(it + 1);

        const uint32_t aBase = sb + (uint32_t)(it & 1) * BUF_BYTES;
        const uint32_t bBase = aBase + 16384;

        #pragma unroll
        for (int ks = 0; ks < 4; ++ks) {
            const int bytecol = ks * 32 + khalf * 16;
            uint32_t afr[4][4], bfr[2][4];
            #pragma unroll
            for (int im = 0; im < 4; ++im) {
                uint32_t addr = aBase +
                    SW128((uint32_t)((m_warp + im * 16 + r_in) * 128 + bytecol));
                LDSM_X4(afr[im], addr);
            }
            #pragma unroll
            for (int j2 = 0; j2 < 2; ++j2) {
                uint32_t addr = bBase +
                    SW128((uint32_t)((n_warp + j2 * 16 + r_in) * 128 + bytecol));
                LDSM_X4(bfr[j2], addr);
            }
            #pragma unroll
            for (int im = 0; im < 4; ++im)
                #pragma unroll
                for (int jn = 0; jn < 4; ++jn)
                    MMA16816(acc[im][jn],
                             afr[im],
                             bfr[jn >> 1][jn & 1],
                             bfr[jn >> 1][(jn & 1) + 2]);
        }
        __syncthreads();
    }

    // --- epilogue: direct register -> gmem float2 stores (+bias)
    const int row_t = lane >> 2;         // 0..7
    const int col_t = (lane & 3) * 2;    // 0,2,4,6
    #pragma unroll
    for (int jn = 0; jn < 4; ++jn) {
        const int gn = n0 + n_warp + jn * 8 + col_t;
        const float bx = __ldg(bias + gn);
        const float by = __ldg(bias + gn + 1);
        #pragma unroll
        for (int im = 0; im < 4; ++im) {
            const int gm = m0 + m_warp + im * 16 + row_t;
            float2 v0 = make_float2(acc[im][jn][0] + bx, acc[im][jn][1] + by);
            float2 v1 = make_float2(acc[im][jn][2] + bx, acc[im][jn][3] + by);
            *(float2*)&out[(size_t)gm * N_TOTAL + gn]       = v0;
            *(float2*)&out[(size_t)(gm + 8) * N_TOTAL + gn] = v1;
        }
    }
}

// ============================ launch ============================
extern "C" void kernel_launch(void* const* d_in, const int* in_sizes, int n_in,
                              void* d_out, int out_size) {
    const float* inp  = (const float*)d_in[0];
    const float* wgt  = (const float*)d_in[1];
    const float* bias = (const float*)d_in[2];
    float* out = (float*)d_out;

    void *qx_p = nullptr, *qw_p = nullptr;
    cudaGetSymbolAddress(&qx_p, g_qx);
    cudaGetSymbolAddress(&qw_p, g_qw);

    cudaFuncSetAttribute(bfp_gemm, cudaFuncAttributeMaxDynamicSharedMemorySize,
                         SMEM_BYTES);

    const int ngroups_in = (M_TOTAL * K_TOTAL) / GSIZE;   // 1048576
    const int ngroups_w  = (N_TOTAL * K_TOTAL) / GSIZE;   // 589824

    bfp_quant<<<ngroups_in / 8, 256>>>(inp, (__nv_bfloat16*)qx_p, ngroups_in);
    bfp_quant<<<ngroups_w  / 8, 256>>>(wgt, (__nv_bfloat16*)qw_p, ngroups_w);

    dim3 grid(N_TOTAL / BN, M_TOTAL / BM);   // (36, 64)
    bfp_gemm<<<grid, 256, SMEM_BYTES>>>(bias, out);
}

// round 3
// speedup vs baseline: 1.0692x; 1.0692x over previous
#include <cuda_runtime.h>
#include <cuda_bf16.h>
#include <cstdint>

#define M_TOTAL 8192
#define K_TOTAL 4608
#define N_TOTAL 4608
#define GSIZE   36

// -------- device scratch (static: no allocation in kernel_launch) --------
__device__ __nv_bfloat16 g_qx[(size_t)M_TOTAL * K_TOTAL];  // 75.5 MB
__device__ __nv_bfloat16 g_qw[(size_t)N_TOTAL * K_TOTAL];  // 42.5 MB

// ============================ helpers ============================
__device__ __forceinline__ uint32_t smem_u32(const void* p) {
    uint32_t a;
    asm("{ .reg .u64 t; cvta.to.shared.u64 t, %1; cvt.u32.u64 %0, t; }"
        : "=r"(a) : "l"(p));
    return a;
}

#define SW128(o) ((o) ^ (((o) >> 3) & 0x70))

__device__ __forceinline__ void cp16(uint32_t saddr, const void* g) {
    asm volatile("cp.async.cg.shared.global [%0], [%1], 16;"
                 :: "r"(saddr), "l"(g) : "memory");
}
#define CP_COMMIT() asm volatile("cp.async.commit_group;" ::: "memory")
#define CP_WAIT1()  asm volatile("cp.async.wait_group 1;" ::: "memory")

#define LDSM_X4(r, addr) \
    asm volatile("ldmatrix.sync.aligned.m8n8.x4.shared.b16 {%0,%1,%2,%3}, [%4];" \
        : "=r"((r)[0]), "=r"((r)[1]), "=r"((r)[2]), "=r"((r)[3]) : "r"(addr))

#define MMA16816(d, a, b0, b1) \
    asm volatile("mma.sync.aligned.m16n8k16.row.col.f32.bf16.bf16.f32 " \
        "{%0,%1,%2,%3}, {%4,%5,%6,%7}, {%8,%9}, {%0,%1,%2,%3};" \
        : "+f"((d)[0]), "+f"((d)[1]), "+f"((d)[2]), "+f"((d)[3]) \
        : "r"((a)[0]), "r"((a)[1]), "r"((a)[2]), "r"((a)[3]), "r"(b0), "r"(b1))

// ============================ Quantize ============================
// Block-staged: 256 groups (9216 floats = 36 KB) per block.
// Coalesced float4 global loads -> SMEM; one thread per group reads its
// 36 floats as 9 conflict-free float4s (lane start banks 4t mod 32 cover
// all 32 banks exactly once per 8-lane phase); quantize; restage as bf16;
// coalesced uint4 stores.
// Exactness: shared exponent = fp32 exponent field of absmax; trunc/scale
// by powers of two exact; result has <=8 significand bits -> exact in bf16.
__global__ void __launch_bounds__(256) bfp_quant(const float* __restrict__ in,
                                                 __nv_bfloat16* __restrict__ out) {
    __shared__ float s[9216];
    const int tid = threadIdx.x;
    const size_t base = (size_t)blockIdx.x * 9216;

    const float4* in4 = (const float4*)(in + base);
    float4* s4 = (float4*)s;
    #pragma unroll
    for (int j = 0; j < 9; ++j)
        s4[j * 256 + tid] = in4[j * 256 + tid];
    __syncthreads();

    float4 v[9];
    const float4* g4 = (const float4*)(s + tid * GSIZE);
    float m = 0.0f;
    #pragma unroll
    for (int i = 0; i < 9; ++i) {
        v[i] = g4[i];
        m = fmaxf(m, fmaxf(fmaxf(fabsf(v[i].x), fabsf(v[i].y)),
                           fmaxf(fabsf(v[i].z), fabsf(v[i].w))));
    }
    if (m > 0.0f) {
        int e = (int)((__float_as_uint(m) >> 23) & 0xFF) - 127;
        float stp = __int_as_float((uint32_t)(e - 7 + 127) << 23);  // 2^(e-7)
        float inv = __int_as_float((uint32_t)(7 - e + 127) << 23);  // 2^(7-e)
        #pragma unroll
        for (int i = 0; i < 9; ++i) {
            v[i].x = truncf(v[i].x * inv) * stp;
            v[i].y = truncf(v[i].y * inv) * stp;
            v[i].z = truncf(v[i].z * inv) * stp;
            v[i].w = truncf(v[i].w * inv) * stp;
        }
    }
    __syncthreads();   // all reads of s done before overwrite

    __nv_bfloat162* s2 = (__nv_bfloat162*)s;
    #pragma unroll
    for (int i = 0; i < 9; ++i) {
        s2[tid * 18 + 2 * i]     = __nv_bfloat162(__float2bfloat16(v[i].x),
                                                  __float2bfloat16(v[i].y));
        s2[tid * 18 + 2 * i + 1] = __nv_bfloat162(__float2bfloat16(v[i].z),
                                                  __float2bfloat16(v[i].w));
    }
    __syncthreads();

    // 9216 bf16 = 18432 B = 1152 uint4
    uint4* o4 = (uint4*)(out + base);
    const uint4* so4 = (const uint4*)s;
    #pragma unroll
    for (int j = 0; j < 4; ++j)
        o4[j * 256 + tid] = so4[j * 256 + tid];
    if (tid < 128) o4[1024 + tid] = so4[1024 + tid];
}

// ============================ GEMM ============================
// D[8192,4608] = qx @ qw^T + bias   (TN: both operands K-major)
// CTA: 256x128 tile, BK=64, 512 threads = 16 warps (4M x 4N),
// warp tile 64x32. 3-stage cp.async ring buffer (48KB/stage, 144KB).
#define BM 256
#define BN 128
#define BK 64
#define KITERS (K_TOTAL / BK)       // 72
#define A_BYTES 32768               // 256 rows x 128 B
#define B_BYTES 16384               // 128 rows x 128 B
#define STAGE_BYTES (A_BYTES + B_BYTES)   // 49152
#define NSTAGE 3
#define SMEM_BYTES (NSTAGE * STAGE_BYTES) // 147456

__global__ void __launch_bounds__(512, 1)
bfp_gemm(const float* __restrict__ bias, float* __restrict__ out) {
    extern __shared__ char smem[];
    const uint32_t sb = smem_u32(smem);
    const int tid  = threadIdx.x;
    const int wid  = tid >> 5;
    const int lane = tid & 31;
    const int n0 = blockIdx.x * BN;
    const int m0 = blockIdx.y * BM;

    const int m_warp = (wid & 3) * 64;   // 4 warps along M
    const int n_warp = (wid >> 2) * 32;  // 4 warps along N

    const __nv_bfloat16* Ag = g_qx + (size_t)m0 * K_TOTAL;
    const __nv_bfloat16* Bg = g_qw + (size_t)n0 * K_TOTAL;

    // tile loader: A[256 x 64] + B[128 x 64] bf16, SW128 rows of 128 B
    const int ldr = tid >> 3;        // 0..63
    const int ldc = tid & 7;         // 16B chunk
    const uint32_t soff0 = SW128((uint32_t)(ldr * 128 + ldc * 16));
    auto load_tiles = [&](int it, int stage) {
        const __nv_bfloat16* Ak = Ag + it * BK;
        const __nv_bfloat16* Bk = Bg + it * BK;
        const uint32_t base = sb + (uint32_t)stage * STAGE_BYTES;
        #pragma unroll
        for (int j = 0; j < 4; ++j) {
            int r = ldr + j * 64;
            cp16(base + soff0 + j * 64 * 128,
                 Ak + (size_t)r * K_TOTAL + ldc * 8);
        }
        #pragma unroll
        for (int j = 0; j < 2; ++j) {
            int r = ldr + j * 64;
            cp16(base + A_BYTES + soff0 + j * 64 * 128,
                 Bk + (size_t)r * K_TOTAL + ldc * 8);
        }
        CP_COMMIT();
    };

    float acc[4][4][4];
    #pragma unroll
    for (int i = 0; i < 4; ++i)
        #pragma unroll
        for (int j = 0; j < 4; ++j)
            #pragma unroll
            for (int c = 0; c < 4; ++c) acc[i][j][c] = 0.0f;

    load_tiles(0, 0);
    load_tiles(1, 1);

    // ldmatrix lane addressing (x4)
    const int r_in  = (lane & 7) + ((lane >> 3) & 1) * 8;
    const int khalf = lane >> 4;

    int stage = 0;
    for (int it = 0; it < KITERS; ++it) {
        CP_WAIT1();            // group(it) complete
        __syncthreads();       // + everyone done computing slot being reloaded

        if (it + 2 < KITERS) {
            int ls = stage + 2; if (ls >= NSTAGE) ls -= NSTAGE;
            load_tiles(it + 2, ls);
        }

        const uint32_t aBase = sb + (uint32_t)stage * STAGE_BYTES;
        const uint32_t bBase = aBase + A_BYTES;

        #pragma unroll
        for (int ks = 0; ks < 4; ++ks) {
            const int bytecol = ks * 32 + khalf * 16;
            uint32_t afr[4][4], bfr[2][4];
            #pragma unroll
            for (int im = 0; im < 4; ++im) {
                uint32_t addr = aBase +
                    SW128((uint32_t)((m_warp + im * 16 + r_in) * 128 + bytecol));
                LDSM_X4(afr[im], addr);
            }
            #pragma unroll
            for (int j2 = 0; j2 < 2; ++j2) {
                uint32_t addr = bBase +
                    SW128((uint32_t)((n_warp + j2 * 16 + r_in) * 128 + bytecol));
                LDSM_X4(bfr[j2], addr);
            }
            #pragma unroll
            for (int im = 0; im < 4; ++im)
                #pragma unroll
                for (int jn = 0; jn < 4; ++jn)
                    MMA16816(acc[im][jn],
                             afr[im],
                             bfr[jn >> 1][jn & 1],
                             bfr[jn >> 1][(jn & 1) + 2]);
        }
        stage = (stage + 1 == NSTAGE) ? 0 : stage + 1;
    }

    // --- epilogue: direct register -> gmem float2 stores (+bias)
    const int row_t = lane >> 2;         // 0..7
    const int col_t = (lane & 3) * 2;    // 0,2,4,6
    #pragma unroll
    for (int jn = 0; jn < 4; ++jn) {
        const int gn = n0 + n_warp + jn * 8 + col_t;
        const float bx = __ldg(bias + gn);
        const float by = __ldg(bias + gn + 1);
        #pragma unroll
        for (int im = 0; im < 4; ++im) {
            const int gm = m0 + m_warp + im * 16 + row_t;
            float2 v0 = make_float2(acc[im][jn][0] + bx, acc[im][jn][1] + by);
            float2 v1 = make_float2(acc[im][jn][2] + bx, acc[im][jn][3] + by);
            *(float2*)&out[(size_t)gm * N_TOTAL + gn]       = v0;
            *(float2*)&out[(size_t)(gm + 8) * N_TOTAL + gn] = v1;
        }
    }
}

// ============================ launch ============================
extern "C" void kernel_launch(void* const* d_in, const int* in_sizes, int n_in,
                              void* d_out, int out_size) {
    const float* inp  = (const float*)d_in[0];
    const float* wgt  = (const float*)d_in[1];
    const float* bias = (const float*)d_in[2];
    float* out = (float*)d_out;

    void *qx_p = nullptr, *qw_p = nullptr;
    cudaGetSymbolAddress(&qx_p, g_qx);
    cudaGetSymbolAddress(&qw_p, g_qw);

    cudaFuncSetAttribute(bfp_gemm, cudaFuncAttributeMaxDynamicSharedMemorySize,
                         SMEM_BYTES);

    // 256 groups per block
    const int nblk_in = (M_TOTAL * K_TOTAL) / (GSIZE * 256);  // 4096
    const int nblk_w  = (N_TOTAL * K_TOTAL) / (GSIZE * 256);  // 2304

    bfp_quant<<<nblk_in, 256>>>(inp, (__nv_bfloat16*)qx_p);
    bfp_quant<<<nblk_w,  256>>>(wgt, (__nv_bfloat16*)qw_p);

    dim3 grid(N_TOTAL / BN, M_TOTAL / BM);   // (36, 32)
    bfp_gemm<<<grid, 512, SMEM_BYTES>>>(bias, out);
}